// round 15
// baseline (speedup 1.0000x reference)
#include <cuda_runtime.h>
#include <cuda_bf16.h>
#include <math.h>
#include <stdint.h>

// GPT-2 small fwd: B=2 T=1024 E=768 H=12 L=6 V=50257
#define NB 2
#define NTOK 1024
#define NE 768
#define NH 12
#define DH 64
#define NL 6
#define NV 50257
#define NM (NB*NTOK)
#define N3 (3*NE)
#define N4 (4*NE)
#define NBH (NB*NH)

#define LQKV (N3*NE)
#define LWO  (NE*NE)
#define LWFC (N4*NE)
#define LWPR (NE*N4)
#define LTF  (LWO+LWFC+LWPR)

#define NTN 393
#define NTP (NTN*4)

#define PAD 48   // fp32 smem row pad: stride 192B, ≡16 mod 32 floats (conflict-free LDS.128)

typedef __nv_bfloat16 bf16;

// K-permutation within each 16-group: new position of old in-group col q.
// Thread tg's k16 fragment (old cols tg, tg+4, tg+8, tg+12) lands at 4tg..4tg+3.
__device__ __forceinline__ int P16(int q) { return 4 * (q & 3) + (q >> 2); }

// ---------------- scratch ------------------------------------------------------
static __device__ float g_x  [NM*NE];
static __device__ float g_logits[(size_t)NM*NV];
static __device__ float g_rl [NM];
static __device__ float g_pm [(size_t)NM*NTP];
static __device__ float g_ps [(size_t)NM*NTP];
static __device__ float g_wtef[(size_t)NV*NE];         // tf32 wte, K16-permuted
static __device__ float g_lnf[NM*NE];                  // tf32 LN out, K16-permuted
static __device__ float g_wtf[(size_t)NL*LTF];         // tf32 Wo/Wfc/Wproj^T, K16-permuted
static __device__ float g_wtfq[(size_t)NL*LQKV];       // tf32 Wqkv^T, K16-permuted
static __device__ float g_yf [NM*NE];                  // attn out, K16-permuted
static __device__ float g_fcf[(size_t)NM*N4];          // FC gelu out, K16-permuted
static __device__ float g_po [(size_t)2*NBH*8*4096];
static __device__ float g_pmx[2*NBH*8*64];
static __device__ float g_pll[2*NBH*8*64];
static __device__ bf16 g_qkvh[NM*N3];
static __device__ bf16 g_qkvl[NM*N3];

// ---------------- helpers -------------------------------------------------------
__device__ __forceinline__ uint32_t packbf(float a, float b) {
    __nv_bfloat162 t;
    t.x = __float2bfloat16(a);
    t.y = __float2bfloat16(b);
    return *(uint32_t*)&t;
}
__device__ __forceinline__ uint32_t smem_u32(const void* p) {
    uint32_t a;
    asm("{ .reg .u64 t; cvta.to.shared.u64 t, %1; cvt.u32.u64 %0, t; }" : "=r"(a) : "l"(p));
    return a;
}
__device__ __forceinline__ uint32_t tf32r(float v) {
    uint32_t u;
    asm("cvt.rna.tf32.f32 %0, %1;" : "=r"(u) : "f"(v));
    return u;
}
__device__ __forceinline__ void cpa16(void* dst, const void* src) {
    uint32_t d = (uint32_t)__cvta_generic_to_shared(dst);
    asm volatile("cp.async.cg.shared.global [%0], [%1], 16;" :: "r"(d), "l"(src));
}
__device__ __forceinline__ void cpa16u(uint32_t d, const void* src) {
    asm volatile("cp.async.cg.shared.global [%0], [%1], 16;" :: "r"(d), "l"(src));
}
__device__ __forceinline__ void cpa16z(void* dst, const void* src, int sz) {
    uint32_t d = (uint32_t)__cvta_generic_to_shared(dst);
    asm volatile("cp.async.cg.shared.global [%0], [%1], 16, %2;" :: "r"(d), "l"(src), "r"(sz));
}
#define CP_COMMIT() asm volatile("cp.async.commit_group;")
#define CP_WAIT(n)  asm volatile("cp.async.wait_group %0;" :: "n"(n))

#define MMA16816(c, a, b) \
    asm volatile("mma.sync.aligned.m16n8k16.row.col.f32.bf16.bf16.f32 " \
                 "{%0,%1,%2,%3}, {%4,%5,%6,%7}, {%8,%9}, {%0,%1,%2,%3};" \
                 : "+f"((c)[0]), "+f"((c)[1]), "+f"((c)[2]), "+f"((c)[3]) \
                 : "r"((a)[0]), "r"((a)[1]), "r"((a)[2]), "r"((a)[3]), \
                   "r"((b)[0]), "r"((b)[1]))

#define MMATF32(c, a0, a1, a2, a3, b0, b1) \
    asm volatile("mma.sync.aligned.m16n8k8.row.col.f32.tf32.tf32.f32 " \
                 "{%0,%1,%2,%3}, {%4,%5,%6,%7}, {%8,%9}, {%0,%1,%2,%3};" \
                 : "+f"((c)[0]), "+f"((c)[1]), "+f"((c)[2]), "+f"((c)[3]) \
                 : "r"(a0), "r"(a1), "r"(a2), "r"(a3), "r"(b0), "r"(b1))

#define LDMX4(r0, r1, r2, r3, a) \
    asm volatile("ldmatrix.sync.aligned.m8n8.x4.shared.b16 {%0,%1,%2,%3}, [%4];" \
                 : "=r"(r0), "=r"(r1), "=r"(r2), "=r"(r3) : "r"(a))
#define LDMX4T(r0, r1, r2, r3, a) \
    asm volatile("ldmatrix.sync.aligned.m8n8.x4.trans.shared.b16 {%0,%1,%2,%3}, [%4];" \
                 : "=r"(r0), "=r"(r1), "=r"(r2), "=r"(r3) : "r"(a))

__device__ __forceinline__ float gelu_tanh(float x) {
    const float c = 0.7978845608028654f;
    float x3 = x * x * x;
    return 0.5f * x * (1.0f + tanhf(c * (x + 0.044715f * x3)));
}
__device__ __forceinline__ void lse_merge(float& m, float& s, float m2, float s2) {
    float M = fmaxf(m, m2);
    if (M == -INFINITY) { m = M; s = 0.f; return; }
    float e1 = (m  == -INFINITY) ? 0.f : expf(m  - M);
    float e2 = (m2 == -INFINITY) ? 0.f : expf(m2 - M);
    s = s * e1 + s2 * e2;
    m = M;
}

// ---------------- embed ---------------------------------------------------------
__global__ void embed_kernel(const int* __restrict__ x0,
                             const float* __restrict__ wte,
                             const float* __restrict__ wpe,
                             float* __restrict__ x) {
    int i = blockIdx.x * blockDim.x + threadIdx.x;
    if (i >= NM * NE) return;
    int tok = i / NE, e = i - tok * NE;
    int t = tok % NTOK;
    int id = x0[tok];
    x[i] = wte[(size_t)id * NE + e] + wpe[(size_t)t * NE + e];
}

// ---------------- layernorm -> tf32 fp32, K16-permuted output ----------------------
__global__ void __launch_bounds__(256) ln_f32(const float* __restrict__ x,
                                              const float* __restrict__ w,
                                              const float* __restrict__ b,
                                              float* __restrict__ out) {
    int warp = threadIdx.x >> 5, lane = threadIdx.x & 31;
    int tok = blockIdx.x * 8 + warp;
    const float* row = x + (size_t)tok * NE;

    float v[24];
    float s = 0.f;
#pragma unroll
    for (int j = 0; j < 6; ++j) {
        float4 f = *(const float4*)(row + j * 128 + lane * 4);
        v[4*j] = f.x; v[4*j+1] = f.y; v[4*j+2] = f.z; v[4*j+3] = f.w;
        s += (f.x + f.y) + (f.z + f.w);
    }
#pragma unroll
    for (int o = 16; o > 0; o >>= 1) s += __shfl_xor_sync(0xFFFFFFFFu, s, o);
    float mean = s * (1.0f / NE);

    float var = 0.f;
#pragma unroll
    for (int i = 0; i < 24; ++i) { float d = v[i] - mean; var += d * d; }
#pragma unroll
    for (int o = 16; o > 0; o >>= 1) var += __shfl_xor_sync(0xFFFFFFFFu, var, o);
    float rstd = rsqrtf(var * (1.0f / NE) + 1e-6f);

    // old col = j*128 + lane*4 + i: in-group q = (lane&3)*4+i -> P16(q) = 4i + (lane&3)
    int gb = (lane >> 2) * 16 + (lane & 3);
#pragma unroll
    for (int j = 0; j < 6; ++j) {
        float4 w4 = *(const float4*)(w + j * 128 + lane * 4);
        float4 b4 = *(const float4*)(b + j * 128 + lane * 4);
        float* o = out + (size_t)tok * NE + j * 128 + gb;
        *(uint32_t*)(o + 0)  = tf32r((v[4*j]   - mean) * rstd * w4.x + b4.x);
        *(uint32_t*)(o + 4)  = tf32r((v[4*j+1] - mean) * rstd * w4.y + b4.y);
        *(uint32_t*)(o + 8)  = tf32r((v[4*j+2] - mean) * rstd * w4.z + b4.z);
        *(uint32_t*)(o + 12) = tf32r((v[4*j+3] - mean) * rstd * w4.w + b4.w);
    }
}

// ---------------- tf32 round + K16-permute (wte) -----------------------------------
// thread handles one 16-group
__global__ void tf32round(const float* __restrict__ x, float* __restrict__ y, int n16) {
    int i = blockIdx.x * blockDim.x + threadIdx.x;
    if (i >= n16) return;
    float4 a = ((const float4*)x)[i * 4];
    float4 b = ((const float4*)x)[i * 4 + 1];
    float4 c = ((const float4*)x)[i * 4 + 2];
    float4 d = ((const float4*)x)[i * 4 + 3];
    uint4 w0, w1, w2, w3;
    w0.x = tf32r(a.x); w0.y = tf32r(b.x); w0.z = tf32r(c.x); w0.w = tf32r(d.x);
    w1.x = tf32r(a.y); w1.y = tf32r(b.y); w1.z = tf32r(c.y); w1.w = tf32r(d.y);
    w2.x = tf32r(a.z); w2.y = tf32r(b.z); w2.z = tf32r(c.z); w2.w = tf32r(d.z);
    w3.x = tf32r(a.w); w3.y = tf32r(b.w); w3.z = tf32r(c.w); w3.w = tf32r(d.w);
    ((uint4*)y)[i * 4]     = w0;
    ((uint4*)y)[i * 4 + 1] = w1;
    ((uint4*)y)[i * 4 + 2] = w2;
    ((uint4*)y)[i * 4 + 3] = w3;
}

// ---------------- transpose + tf32 + K16-permute (weights): in[K,N] -> out[N,K] ----
__global__ void __launch_bounds__(256) ttf32(const float* __restrict__ in,
                                             float* __restrict__ out,
                                             int K, int N) {
    __shared__ float t[32][65];
    int tid = threadIdx.x;
    int kb = blockIdx.y * 32, nb = blockIdx.x * 64;
#pragma unroll
    for (int i = 0; i < 2; ++i) {
        int id = tid + 256 * i;
        int r = id >> 4, c4 = (id & 15) * 4;
        float4 v = *(const float4*)(in + (size_t)(kb + r) * N + nb + c4);
        t[r][c4] = v.x; t[r][c4+1] = v.y; t[r][c4+2] = v.z; t[r][c4+3] = v.w;
    }
    __syncthreads();
#pragma unroll
    for (int i = 0; i < 8; ++i) {
        int id = tid + 256 * i;
        int n = id >> 5, kp = id & 31;
        uint32_t o = tf32r(t[kp][n]);
        int kpp = (kp & 16) | P16(kp & 15);
        *(uint32_t*)(out + (size_t)(nb + n) * K + kb + kpp) = o;
    }
}

// ---------------- TF32 GEMM (K16-permuted operands, LDS.128 fragments) --------------
// EPI: 0 = split-bf16 out; 1 = +R fp32 out; 2 = gelu tf32 K16-permuted out;
//      3 = fp32 out + lse partials. BN = 128 or 64.
template<int EPI, int BN>
__global__ void __launch_bounds__(256, 2) gemm_t32(
    const float* __restrict__ A, const float* __restrict__ B,
    float* __restrict__ C, bf16* __restrict__ Ch, bf16* __restrict__ Cl,
    const float* __restrict__ R,
    float* __restrict__ PM, float* __restrict__ PS,
    int M, int N, int K)
{
    constexpr int NT = BN / 32;
    extern __shared__ __align__(16) float smf[];
    float* As = smf;                     // [2][128][PAD]
    float* Bs = smf + 2 * 128 * PAD;     // [2][BN][PAD]
    const uint32_t* Au = (const uint32_t*)As;
    const uint32_t* Bu = (const uint32_t*)Bs;

    const int tid = threadIdx.x;
    const int lane = tid & 31, wid = tid >> 5;
    const int wm = wid >> 2, wn = wid & 3;
    const int g = lane >> 2, tg = lane & 3;
    const int m0 = blockIdx.x * 128;
    const int n0 = blockIdx.y * BN;

    float acc[4][NT][4];
#pragma unroll
    for (int a = 0; a < 4; ++a)
#pragma unroll
        for (int b = 0; b < NT; ++b)
#pragma unroll
            for (int c = 0; c < 4; ++c) acc[a][b][c] = 0.f;

    auto load_stage = [&](int st, int k0) {
#pragma unroll
        for (int i = 0; i < 4; ++i) {
            int id = tid + 256 * i;
            int r = id >> 3, u = id & 7;
            cpa16(&As[(st * 128 + r) * PAD + u * 4], A + (size_t)(m0 + r) * K + k0 + u * 4);
        }
#pragma unroll
        for (int i = 0; i < BN / 32; ++i) {
            int id = tid + 256 * i;
            int r = id >> 3, u = id & 7;
            int n = n0 + r;
            int ok = n < N;
            cpa16z(&Bs[(st * BN + r) * PAD + u * 4],
                   B + (size_t)(ok ? n : 0) * K + k0 + u * 4, ok ? 16 : 0);
        }
    };

    load_stage(0, 0);
    CP_COMMIT();
    const int nk = K / 32;
    for (int it = 0; it < nk; ++it) {
        int st = it & 1;
        if (it + 1 < nk) { load_stage(st ^ 1, (it + 1) * 32); CP_COMMIT(); CP_WAIT(1); }
        else            { CP_WAIT(0); }
        __syncthreads();
#pragma unroll
        for (int k16 = 0; k16 < 32; k16 += 16) {
            uint4 bv[NT];
#pragma unroll
            for (int nt = 0; nt < NT; ++nt) {
                int row = st * BN + wn * (BN / 4) + nt * 8 + g;
                bv[nt] = *(const uint4*)&Bu[row * PAD + k16 + 4 * tg];
            }
#pragma unroll
            for (int mt = 0; mt < 4; ++mt) {
                int row = st * 128 + wm * 64 + mt * 16 + g;
                uint4 aA = *(const uint4*)&Au[row * PAD + k16 + 4 * tg];
                uint4 aB = *(const uint4*)&Au[(row + 8) * PAD + k16 + 4 * tg];
#pragma unroll
                for (int nt = 0; nt < NT; ++nt) {
                    MMATF32(acc[mt][nt], aA.x, aB.x, aA.y, aB.y, bv[nt].x, bv[nt].y);
                    MMATF32(acc[mt][nt], aA.z, aB.z, aA.w, aB.w, bv[nt].z, bv[nt].w);
                }
            }
        }
        __syncthreads();
    }

    if (EPI == 3) {
        int tile = blockIdx.y * 4 + wn;
#pragma unroll
        for (int mt = 0; mt < 4; ++mt) {
#pragma unroll
            for (int r = 0; r < 2; ++r) {
                int m = m0 + wm * 64 + mt * 16 + g + 8 * r;
                float vals[2 * NT];
                float rm = -INFINITY;
#pragma unroll
                for (int nt = 0; nt < NT; ++nt)
#pragma unroll
                    for (int j = 0; j < 2; ++j) {
                        int n = n0 + wn * (BN / 4) + nt * 8 + 2 * tg + j;
                        float v = acc[mt][nt][2 * r + j];
                        if (n < N) {
                            C[(size_t)m * N + n] = v;
                            rm = fmaxf(rm, v);
                            vals[nt * 2 + j] = v;
                        } else {
                            vals[nt * 2 + j] = -INFINITY;
                        }
                    }
                rm = fmaxf(rm, __shfl_xor_sync(0xFFFFFFFFu, rm, 1));
                rm = fmaxf(rm, __shfl_xor_sync(0xFFFFFFFFu, rm, 2));
                float s = 0.f;
                if (rm != -INFINITY) {
#pragma unroll
                    for (int i = 0; i < 2 * NT; ++i)
                        s += (vals[i] == -INFINITY) ? 0.f : expf(vals[i] - rm);
                }
                s += __shfl_xor_sync(0xFFFFFFFFu, s, 1);
                s += __shfl_xor_sync(0xFFFFFFFFu, s, 2);
                if (tg == 0) {
                    PM[(size_t)m * NTP + tile] = rm;
                    PS[(size_t)m * NTP + tile] = s;
                }
            }
        }
        return;
    }

#pragma unroll
    for (int mt = 0; mt < 4; ++mt) {
#pragma unroll
        for (int nt = 0; nt < NT; ++nt) {
            int nbase = n0 + wn * (BN / 4) + nt * 8 + 2 * tg;
#pragma unroll
            for (int r = 0; r < 2; ++r) {
                int m = m0 + wm * 64 + mt * 16 + g + 8 * r;
                float v0 = acc[mt][nt][2 * r + 0];
                float v1 = acc[mt][nt][2 * r + 1];
                if (EPI == 0) {
                    bf16 h0 = __float2bfloat16(v0);
                    bf16 h1 = __float2bfloat16(v1);
                    __nv_bfloat162 hp; hp.x = h0; hp.y = h1;
                    *(uint32_t*)(Ch + (size_t)m * N + nbase) = *(uint32_t*)&hp;
                    *(uint32_t*)(Cl + (size_t)m * N + nbase) =
                        packbf(v0 - __bfloat162float(h0), v1 - __bfloat162float(h1));
                } else if (EPI == 1) {
                    v0 += R[(size_t)m * N + nbase];
                    v1 += R[(size_t)m * N + nbase + 1];
                    C[(size_t)m * N + nbase]     = v0;
                    C[(size_t)m * N + nbase + 1] = v1;
                } else {  // EPI == 2: gelu, K16-permuted store (feeds Proj's K)
                    int c0 = (nbase & ~15) | P16(nbase & 15);
                    int c1 = ((nbase + 1) & ~15) | P16((nbase + 1) & 15);
                    *(uint32_t*)(C + (size_t)m * N + c0) = tf32r(gelu_tanh(v0));
                    *(uint32_t*)(C + (size_t)m * N + c1) = tf32r(gelu_tanh(v1));
                }
            }
        }
    }
}

// ---------------- flash attention with split-KV load balancing ---------------------
#define FP2 72
#define FTILE (64*FP2)
#define FSTG (4*FTILE)
#define FSMEM (2*FSTG*2)

__global__ void __launch_bounds__(128) flash2(
    const bf16* __restrict__ qh, const bf16* __restrict__ ql,
    float* __restrict__ yf, float* __restrict__ po,
    float* __restrict__ pmx, float* __restrict__ pll)
{
    extern __shared__ bf16 fsm[];
    const int u = blockIdx.x;
    const int bh = blockIdx.y, b = bh / NH, h = bh % NH;
    int qt, sb0, sb1, mode;
    if (u < 8)       { mode = 1; qt = 8 + u;        sb0 = 0; sb1 = 7;  }
    else if (u < 16) { mode = 2; qt = 15 - (u - 8); sb0 = 8; sb1 = qt; }
    else             { mode = 0; qt = 23 - u;       sb0 = 0; sb1 = qt; }
    const int t0 = qt * 64;
    const int tid = threadIdx.x, lane = tid & 31, w = tid >> 5;
    const int g = lane >> 2, tg = lane & 3;
    const uint32_t smb = smem_u32(fsm);

    uint32_t qfh[4][4], qfl[4][4];
    {
        const size_t base = (size_t)(b * NTOK + t0 + w * 16) * N3 + h * DH;
#pragma unroll
        for (int kf = 0; kf < 4; ++kf) {
            int c0 = kf * 16 + 2 * tg;
            qfh[kf][0] = *(const uint32_t*)(qh + base + (size_t)g * N3 + c0);
            qfh[kf][1] = *(const uint32_t*)(qh + base + (size_t)(g + 8) * N3 + c0);
            qfh[kf][2] = *(const uint32_t*)(qh + base + (size_t)g * N3 + c0 + 8);
            qfh[kf][3] = *(const uint32_t*)(qh + base + (size_t)(g + 8) * N3 + c0 + 8);
            qfl[kf][0] = *(const uint32_t*)(ql + base + (size_t)g * N3 + c0);
            qfl[kf][1] = *(const uint32_t*)(ql + base + (size_t)(g + 8) * N3 + c0);
            qfl[kf][2] = *(const uint32_t*)(ql + base + (size_t)g * N3 + c0 + 8);
            qfl[kf][3] = *(const uint32_t*)(ql + base + (size_t)(g + 8) * N3 + c0 + 8);
        }
    }

    auto loadKV = [&](int st, int sb) {
        int s0 = sb * 64;
#pragma unroll
        for (int i = 0; i < 16; ++i) {
            int id = tid + 128 * i;
            int tile = id >> 9;
            int rem = id & 511;
            int r = rem >> 3, c8 = (rem & 7) * 8;
            uint32_t dst = smb + (uint32_t)(st * FSTG + tile * FTILE + r * FP2 + c8) * 2;
            size_t rowoff = (size_t)(b * NTOK + s0 + r) * N3 + h * DH + c8;
            const bf16* src =
                (tile == 0) ? qh + rowoff + NE :
                (tile == 1) ? ql + rowoff + NE :
                (tile == 2) ? qh + rowoff + 2 * NE :
                              ql + rowoff + 2 * NE;
            cpa16u(dst, src);
        }
    };

    float mr[2] = {-1e30f, -1e30f};
    float lr[2] = {0.f, 0.f};
    float acco[8][4];
#pragma unroll
    for (int i = 0; i < 8; ++i)
#pragma unroll
        for (int j = 0; j < 4; ++j) acco[i][j] = 0.f;

    loadKV(0, sb0);
    CP_COMMIT();

    const int krow = ((lane >> 4) << 3) + (lane & 7);
    const int kcol = ((lane >> 3) & 1) * 8;
    const int vrow = lane & 15;
    const int vcol = (lane >> 4) * 8;

    for (int sb = sb0; sb <= sb1; ++sb) {
        int st = (sb - sb0) & 1;
        if (sb + 1 <= sb1) { loadKV(st ^ 1, sb + 1); CP_COMMIT(); CP_WAIT(1); }
        else               { CP_WAIT(0); }
        __syncthreads();

        const uint32_t kb  = smb + (uint32_t)(st * FSTG) * 2;
        const uint32_t kbl = kb + FTILE * 2;
        const uint32_t vb  = kb + 2 * FTILE * 2;
        const uint32_t vbl = kb + 3 * FTILE * 2;

        float accs[8][4];
#pragma unroll
        for (int i = 0; i < 8; ++i)
#pragma unroll
            for (int j = 0; j < 4; ++j) accs[i][j] = 0.f;
#pragma unroll
        for (int ntp = 0; ntp < 4; ++ntp) {
#pragma unroll
            for (int kf = 0; kf < 4; ++kf) {
                uint32_t off = (uint32_t)((ntp * 16 + krow) * FP2 + kf * 16 + kcol) * 2;
                uint32_t h0, h1, h2, h3, l0, l1, l2, l3;
                LDMX4(h0, h1, h2, h3, kb + off);
                LDMX4(l0, l1, l2, l3, kbl + off);
                uint32_t bh0[2] = {h0, h1}, bh1[2] = {h2, h3};
                uint32_t bl0[2] = {l0, l1}, bl1[2] = {l2, l3};
                MMA16816(accs[2*ntp],     qfh[kf], bh0);
                MMA16816(accs[2*ntp + 1], qfh[kf], bh1);
                MMA16816(accs[2*ntp],     qfh[kf], bl0);
                MMA16816(accs[2*ntp + 1], qfh[kf], bl1);
                MMA16816(accs[2*ntp],     qfl[kf], bh0);
                MMA16816(accs[2*ntp + 1], qfl[kf], bh1);
            }
        }

        int s0 = sb * 64;
#pragma unroll
        for (int r = 0; r < 2; ++r) {
            int row = t0 + w * 16 + g + 8 * r;
            float rm = -1e30f;
#pragma unroll
            for (int nt = 0; nt < 8; ++nt) {
#pragma unroll
                for (int j = 0; j < 2; ++j) {
                    int col = s0 + nt * 8 + 2 * tg + j;
                    float v = accs[nt][2 * r + j] * 0.125f;
                    if (col > row) v = -1e30f;
                    accs[nt][2 * r + j] = v;
                    rm = fmaxf(rm, v);
                }
            }
            rm = fmaxf(rm, __shfl_xor_sync(0xFFFFFFFFu, rm, 1));
            rm = fmaxf(rm, __shfl_xor_sync(0xFFFFFFFFu, rm, 2));
            float nm = fmaxf(mr[r], rm);
            float fac = __expf(mr[r] - nm);
            mr[r] = nm;
            float rs = 0.f;
#pragma unroll
            for (int nt = 0; nt < 8; ++nt) {
#pragma unroll
                for (int j = 0; j < 2; ++j) {
                    float p = __expf(accs[nt][2 * r + j] - nm);
                    accs[nt][2 * r + j] = p;
                    rs += p;
                }
            }
            rs += __shfl_xor_sync(0xFFFFFFFFu, rs, 1);
            rs += __shfl_xor_sync(0xFFFFFFFFu, rs, 2);
            lr[r] = lr[r] * fac + rs;
#pragma unroll
            for (int nt = 0; nt < 8; ++nt) {
                acco[nt][2 * r + 0] *= fac;
                acco[nt][2 * r + 1] *= fac;
            }
        }

#pragma unroll
        for (int kf2 = 0; kf2 < 4; ++kf2) {
            uint32_t pah[4], pal[4];
            float p00 = accs[2 * kf2][0],     p01 = accs[2 * kf2][1];
            float p10 = accs[2 * kf2][2],     p11 = accs[2 * kf2][3];
            float p20 = accs[2 * kf2 + 1][0], p21 = accs[2 * kf2 + 1][1];
            float p30 = accs[2 * kf2 + 1][2], p31 = accs[2 * kf2 + 1][3];
            pah[0] = packbf(p00, p01); pah[1] = packbf(p10, p11);
            pah[2] = packbf(p20, p21); pah[3] = packbf(p30, p31);
            __nv_bfloat162* hp;
            hp = (__nv_bfloat162*)&pah[0];
            pal[0] = packbf(p00 - __bfloat162float(hp->x), p01 - __bfloat162float(hp->y));
            hp = (__nv_bfloat162*)&pah[1];
            pal[1] = packbf(p10 - __bfloat162float(hp->x), p11 - __bfloat162float(hp->y));
            hp = (__nv_bfloat162*)&pah[2];
            pal[2] = packbf(p20 - __bfloat162float(hp->x), p21 - __bfloat162float(hp->y));
            hp = (__nv_bfloat162*)&pah[3];
            pal[3] = packbf(p30 - __bfloat162float(hp->x), p31 - __bfloat162float(hp->y));
#pragma unroll
            for (int ntp2 = 0; ntp2 < 4; ++ntp2) {
                uint32_t off = (uint32_t)((kf2 * 16 + vrow) * FP2 + ntp2 * 16 + vcol) * 2;
                uint32_t h0, h1, h2, h3, l0, l1, l2, l3;
                LDMX4T(h0, h1, h2, h3, vb + off);
                LDMX4T(l0, l1, l2, l3, vbl + off);
                uint32_t vh0[2] = {h0, h1}, vh1[2] = {h2, h3};
                uint32_t vl0[2] = {l0, l1}, vl1[2] = {l2, l3};
                MMA16816(acco[2*ntp2],     pah, vh0);
                MMA16816(acco[2*ntp2 + 1], pah, vh1);
                MMA16816(acco[2*ntp2],     pah, vl0);
                MMA16816(acco[2*ntp2 + 1], pah, vl1);
                MMA16816(acco[2*ntp2],     pal, vh0);
                MMA16816(acco[2*ntp2 + 1], pal, vh1);
            }
        }
        __syncthreads();
    }

    if (mode == 0) {
        // y written K16-permuted (feeds Wo GEMM A)
#pragma unroll
        for (int r = 0; r < 2; ++r) {
            float inv = 1.0f / lr[r];
            int row = t0 + w * 16 + g + 8 * r;
            float* dst = yf + (size_t)(b * NTOK + row) * NE + h * DH;
#pragma unroll
            for (int nt2 = 0; nt2 < 8; ++nt2) {
                int oc0 = nt2 * 8 + 2 * tg;
                int c0 = (oc0 & ~15) | P16(oc0 & 15);
                int c1 = ((oc0 + 1) & ~15) | P16((oc0 + 1) & 15);
                *(uint32_t*)(dst + c0) = tf32r(acco[nt2][2 * r + 0] * inv);
                *(uint32_t*)(dst + c1) = tf32r(acco[nt2][2 * r + 1] * inv);
            }
        }
    } else {
        int part = mode - 1;
        size_t unit = ((size_t)part * NBH + bh) * 8 + (qt - 8);
#pragma unroll
        for (int r = 0; r < 2; ++r) {
            int lrow = w * 16 + g + 8 * r;
#pragma unroll
            for (int nt2 = 0; nt2 < 8; ++nt2) {
                float2 o;
                o.x = acco[nt2][2 * r + 0];
                o.y = acco[nt2][2 * r + 1];
                *(float2*)(po + unit * 4096 + lrow * 64 + nt2 * 8 + 2 * tg) = o;
            }
            if (tg == 0) {
                pmx[unit * 64 + lrow] = mr[r];
                pll[unit * 64 + lrow] = lr[r];
            }
        }
    }
}

// merge partials (exact lse combine), write K16-permuted tf32 y
__global__ void __launch_bounds__(256) flash_merge(
    const float* __restrict__ po, const float* __restrict__ pmx,
    const float* __restrict__ pll, float* __restrict__ yf)
{
    int qi = blockIdx.x;
    int bh = blockIdx.y, b = bh / NH, h = bh % NH;
    int row = threadIdx.x >> 2;
    int c0 = (threadIdx.x & 3) * 16;

    size_t ua = (size_t)bh * 8 + qi;
    size_t ub = ((size_t)NBH + bh) * 8 + qi;
    float ma = pmx[ua * 64 + row], la = pll[ua * 64 + row];
    float mb = pmx[ub * 64 + row], lb = pll[ub * 64 + row];
    float M = fmaxf(ma, mb);
    float wa = __expf(ma - M), wb = __expf(mb - M);
    float inv = 1.0f / (wa * la + wb * lb);
    wa *= inv; wb *= inv;

    const float* Oa = po + ua * 4096 + row * 64 + c0;
    const float* Ob = po + ub * 4096 + row * 64 + c0;
    float* dst = yf + (size_t)(b * NTOK + (8 + qi) * 64 + row) * NE + h * DH;
#pragma unroll
    for (int i = 0; i < 16; ++i) {
        float v = wa * Oa[i] + wb * Ob[i];
        int c = c0 + i;
        *(uint32_t*)(dst + (c & ~15) + P16(c & 15)) = tf32r(v);
    }
}

// ---------------- loss: merge logsumexp partials ----------------------------------
__global__ void __launch_bounds__(256) loss_rows2(const float* __restrict__ pm,
                                                  const float* __restrict__ ps,
                                                  const float* __restrict__ logits,
                                                  const int* __restrict__ tgt,
                                                  float* __restrict__ rl) {
    int row = blockIdx.x;
    int tid = threadIdx.x;
    __shared__ float sm[256], ss[256];

    float m = -INFINITY, s = 0.f;
    for (int i = tid; i < NTP; i += 256)
        lse_merge(m, s, pm[(size_t)row * NTP + i], ps[(size_t)row * NTP + i]);
    sm[tid] = m; ss[tid] = s; __syncthreads();
    for (int o = 128; o > 0; o >>= 1) {
        if (tid < o) {
            float mm = sm[tid], sv = ss[tid];
            lse_merge(mm, sv, sm[tid + o], ss[tid + o]);
            sm[tid] = mm; ss[tid] = sv;
        }
        __syncthreads();
    }
    if (tid == 0) {
        float lt = logits[(size_t)row * NV + tgt[row]];
        rl[row] = -(lt - sm[0] - logf(ss[0]));
    }
}

__global__ void __launch_bounds__(256) loss_final(const float* __restrict__ rl,
                                                  float* __restrict__ out) {
    __shared__ float red[256];
    int tid = threadIdx.x;
    float s = 0.f;
    for (int i = tid; i < NM; i += 256) s += rl[i];
    red[tid] = s; __syncthreads();
    for (int o = 128; o > 0; o >>= 1) { if (tid < o) red[tid] += red[tid + o]; __syncthreads(); }
    if (tid == 0) out[0] = red[0] * (1.0f / NM);
}

// ---------------- host orchestration ------------------------------------------------
extern "C" void kernel_launch(void* const* d_in, const int* in_sizes, int n_in,
                              void* d_out, int out_size) {
    const int*   x0    = (const int*)  d_in[0];
    const int*   tgt   = (const int*)  d_in[1];
    const float* wte   = (const float*)d_in[2];
    const float* wpe   = (const float*)d_in[3];
    const float* ln1w  = (const float*)d_in[4];
    const float* ln1b  = (const float*)d_in[5];
    const float* Wqkv  = (const float*)d_in[6];
    const float* Wo    = (const float*)d_in[7];
    const float* ln2w  = (const float*)d_in[8];
    const float* ln2b  = (const float*)d_in[9];
    const float* Wfc   = (const float*)d_in[10];
    const float* Wproj = (const float*)d_in[11];
    const float* lnfw  = (const float*)d_in[12];
    const float* lnfb  = (const float*)d_in[13];

    float *px, *pl, *prl, *ppm, *pps, *pwtef, *plnf, *pwtf, *pwtfq, *pyf, *pfcf;
    float *ppo, *ppmx, *ppll;
    bf16 *pqh, *pql;
    cudaGetSymbolAddress((void**)&px,  g_x);
    cudaGetSymbolAddress((void**)&pl,  g_logits);
    cudaGetSymbolAddress((void**)&prl, g_rl);
    cudaGetSymbolAddress((void**)&ppm, g_pm);
    cudaGetSymbolAddress((void**)&pps, g_ps);
    cudaGetSymbolAddress((void**)&pwtef, g_wtef);
    cudaGetSymbolAddress((void**)&plnf, g_lnf);
    cudaGetSymbolAddress((void**)&pwtf, g_wtf);
    cudaGetSymbolAddress((void**)&pwtfq, g_wtfq);
    cudaGetSymbolAddress((void**)&pyf,  g_yf);
    cudaGetSymbolAddress((void**)&pfcf, g_fcf);
    cudaGetSymbolAddress((void**)&ppo,  g_po);
    cudaGetSymbolAddress((void**)&ppmx, g_pmx);
    cudaGetSymbolAddress((void**)&ppll, g_pll);
    cudaGetSymbolAddress((void**)&pqh, g_qkvh);
    cudaGetSymbolAddress((void**)&pql, g_qkvl);

    const int SM_T128 = (2 * 128 * PAD + 2 * 128 * PAD) * 4;   // 98304 B
    const int SM_T64  = (2 * 128 * PAD + 2 * 64  * PAD) * 4;   // 73728 B
    cudaFuncSetAttribute(gemm_t32<0,128>, cudaFuncAttributeMaxDynamicSharedMemorySize, SM_T128);
    cudaFuncSetAttribute(gemm_t32<1,64>,  cudaFuncAttributeMaxDynamicSharedMemorySize, SM_T64);
    cudaFuncSetAttribute(gemm_t32<2,128>, cudaFuncAttributeMaxDynamicSharedMemorySize, SM_T128);
    cudaFuncSetAttribute(gemm_t32<3,128>, cudaFuncAttributeMaxDynamicSharedMemorySize, SM_T128);
    cudaFuncSetAttribute(flash2, cudaFuncAttributeMaxDynamicSharedMemorySize, FSMEM);

    // ---- layer 0 (QKV GEMM kept as my 4th launch for ncu) ----
    embed_kernel<<<(NM * NE + 255) / 256, 256>>>(x0, wte, wpe, px);
    ttf32<<<dim3(N3 / 64, NE / 32), 256>>>(Wqkv, pwtfq, NE, N3);
    ln_f32<<<NM / 8, 256>>>(px, ln1w, ln1b, plnf);
    gemm_t32<0,128><<<dim3(NM / 128, N3 / 128), 256, SM_T128>>>(
        plnf, pwtfq, nullptr, pqh, pql, nullptr, nullptr, nullptr, NM, N3, NE);
    {
        int n16 = (NV * NE) / 16;
        tf32round<<<(n16 + 255) / 256, 256>>>(wte, pwtef, n16);
    }
    ttf32<<<dim3(NE / 64, NE / 32), 256>>>(Wo, pwtf, NE, NE);
    flash2<<<dim3(24, NBH), 128, FSMEM>>>(pqh, pql, pyf, ppo, ppmx, ppll);
    flash_merge<<<dim3(8, NBH), 256>>>(ppo, ppmx, ppll, pyf);
    ttf32<<<dim3(N4 / 64, NE / 32), 256>>>(Wfc, pwtf + LWO, NE, N4);
    ttf32<<<dim3(NE / 64, N4 / 32), 256>>>(Wproj, pwtf + LWO + LWFC, N4, NE);
    gemm_t32<1,64><<<dim3(NM / 128, NE / 64), 256, SM_T64>>>(
        pyf, pwtf, px, nullptr, nullptr, px, nullptr, nullptr, NM, NE, NE);
    ln_f32<<<NM / 8, 256>>>(px, ln2w, ln2b, plnf);
    gemm_t32<2,128><<<dim3(NM / 128, N4 / 128), 256, SM_T128>>>(
        plnf, pwtf + LWO, pfcf, nullptr, nullptr, nullptr, nullptr, nullptr, NM, N4, NE);
    gemm_t32<1,64><<<dim3(NM / 128, NE / 64), 256, SM_T64>>>(
        pfcf, pwtf + LWO + LWFC, px, nullptr, nullptr, px, nullptr, nullptr, NM, NE, N4);

    // ---- layers 1..5 ----
    for (int l = 1; l < NL; ++l) {
        size_t qoff = (size_t)l * LQKV;
        size_t toff = (size_t)l * LTF;
        ttf32<<<dim3(N3 / 64, NE / 32), 256>>>(
            Wqkv + (size_t)l * NE * N3, pwtfq + qoff, NE, N3);
        ttf32<<<dim3(NE / 64, NE / 32), 256>>>(Wo + (size_t)l * NE * NE, pwtf + toff, NE, NE);
        ttf32<<<dim3(N4 / 64, NE / 32), 256>>>(Wfc + (size_t)l * NE * N4, pwtf + toff + LWO, NE, N4);
        ttf32<<<dim3(NE / 64, N4 / 32), 256>>>(Wproj + (size_t)l * N4 * NE,
                                               pwtf + toff + LWO + LWFC, N4, NE);

        ln_f32<<<NM / 8, 256>>>(px, ln1w + (size_t)l * NE, ln1b + (size_t)l * NE, plnf);
        gemm_t32<0,128><<<dim3(NM / 128, N3 / 128), 256, SM_T128>>>(
            plnf, pwtfq + qoff, nullptr, pqh, pql, nullptr, nullptr, nullptr, NM, N3, NE);
        flash2<<<dim3(24, NBH), 128, FSMEM>>>(pqh, pql, pyf, ppo, ppmx, ppll);
        flash_merge<<<dim3(8, NBH), 256>>>(ppo, ppmx, ppll, pyf);
        gemm_t32<1,64><<<dim3(NM / 128, NE / 64), 256, SM_T64>>>(
            pyf, pwtf + toff, px, nullptr, nullptr, px, nullptr, nullptr, NM, NE, NE);
        ln_f32<<<NM / 8, 256>>>(px, ln2w + (size_t)l * NE, ln2b + (size_t)l * NE, plnf);
        gemm_t32<2,128><<<dim3(NM / 128, N4 / 128), 256, SM_T128>>>(
            plnf, pwtf + toff + LWO, pfcf, nullptr, nullptr, nullptr, nullptr, nullptr,
            NM, N4, NE);
        gemm_t32<1,64><<<dim3(NM / 128, NE / 64), 256, SM_T64>>>(
            pfcf, pwtf + toff + LWO + LWFC, px, nullptr, nullptr, px, nullptr, nullptr,
            NM, NE, N4);
    }

    ln_f32<<<NM / 8, 256>>>(px, lnfw, lnfb, plnf);

    const size_t logits_elems = (size_t)NM * NV;
    float* logits = ((size_t)out_size >= logits_elems) ? (float*)d_out : pl;
    gemm_t32<3,128><<<dim3(NM / 128, NTN), 256, SM_T128>>>(
        plnf, pwtef, logits, nullptr, nullptr, nullptr, ppm, pps, NM, NV, NE);

    loss_rows2<<<NM, 256>>>(ppm, pps, logits, tgt, prl);
    if ((size_t)out_size > logits_elems) {
        loss_final<<<1, 256>>>(prl, (float*)d_out + logits_elems);
    } else if (logits != (float*)d_out) {
        loss_final<<<1, 256>>>(prl, (float*)d_out);
    }
}

// round 16
// speedup vs baseline: 1.0646x; 1.0646x over previous
#include <cuda_runtime.h>
#include <cuda_bf16.h>
#include <math.h>
#include <stdint.h>

// GPT-2 small fwd: B=2 T=1024 E=768 H=12 L=6 V=50257
#define NB 2
#define NTOK 1024
#define NE 768
#define NH 12
#define DH 64
#define NL 6
#define NV 50257
#define NM (NB*NTOK)
#define N3 (3*NE)
#define N4 (4*NE)
#define NBH (NB*NH)

#define LQKV (N3*NE)
#define LWO  (NE*NE)
#define LWFC (N4*NE)
#define LWPR (NE*N4)
#define LTF  (LWO+LWFC+LWPR)

#define NTN 393
#define NTP (NTN*4)

typedef __nv_bfloat16 bf16;

// K-permutation within each 8-group: new position of old in-group col q
__device__ __forceinline__ int QP(int q) { return q < 4 ? 2 * q : 2 * (q - 4) + 1; }

// ---------------- scratch ------------------------------------------------------
static __device__ float g_x  [NM*NE];
static __device__ float g_logits[(size_t)NM*NV];
static __device__ float g_rl [NM];
static __device__ float g_pm [(size_t)NM*NTP];
static __device__ float g_ps [(size_t)NM*NTP];
static __device__ float g_wtef[(size_t)NV*NE];         // tf32 wte, K-permuted
static __device__ float g_lnf[NM*NE];                  // tf32 LN out, K-permuted
static __device__ float g_wtf[(size_t)NL*LTF];         // tf32 Wo/Wfc/Wproj^T, K-permuted
static __device__ float g_wtfq[(size_t)NL*LQKV];       // tf32 Wqkv^T, K-permuted
static __device__ float g_yf [NM*NE];                  // attn out, K-permuted
static __device__ float g_fcf[(size_t)NM*N4];          // FC gelu out, K-permuted
static __device__ float g_po [(size_t)2*NBH*8*4096];
static __device__ float g_pmx[2*NBH*8*64];
static __device__ float g_pll[2*NBH*8*64];
static __device__ bf16 g_qkvh[NM*N3];
static __device__ bf16 g_qkvl[NM*N3];

// ---------------- helpers -------------------------------------------------------
__device__ __forceinline__ uint32_t packbf(float a, float b) {
    __nv_bfloat162 t;
    t.x = __float2bfloat16(a);
    t.y = __float2bfloat16(b);
    return *(uint32_t*)&t;
}
__device__ __forceinline__ uint32_t smem_u32(const void* p) {
    uint32_t a;
    asm("{ .reg .u64 t; cvta.to.shared.u64 t, %1; cvt.u32.u64 %0, t; }" : "=r"(a) : "l"(p));
    return a;
}
__device__ __forceinline__ uint32_t tf32r(float v) {
    uint32_t u;
    asm("cvt.rna.tf32.f32 %0, %1;" : "=r"(u) : "f"(v));
    return u;
}
__device__ __forceinline__ void cpa16(void* dst, const void* src) {
    uint32_t d = (uint32_t)__cvta_generic_to_shared(dst);
    asm volatile("cp.async.cg.shared.global [%0], [%1], 16;" :: "r"(d), "l"(src));
}
__device__ __forceinline__ void cpa16u(uint32_t d, const void* src) {
    asm volatile("cp.async.cg.shared.global [%0], [%1], 16;" :: "r"(d), "l"(src));
}
__device__ __forceinline__ void cpa16z(void* dst, const void* src, int sz) {
    uint32_t d = (uint32_t)__cvta_generic_to_shared(dst);
    asm volatile("cp.async.cg.shared.global [%0], [%1], 16, %2;" :: "r"(d), "l"(src), "r"(sz));
}
#define CP_COMMIT() asm volatile("cp.async.commit_group;")
#define CP_WAIT(n)  asm volatile("cp.async.wait_group %0;" :: "n"(n))

#define MMA16816(c, a, b) \
    asm volatile("mma.sync.aligned.m16n8k16.row.col.f32.bf16.bf16.f32 " \
                 "{%0,%1,%2,%3}, {%4,%5,%6,%7}, {%8,%9}, {%0,%1,%2,%3};" \
                 : "+f"((c)[0]), "+f"((c)[1]), "+f"((c)[2]), "+f"((c)[3]) \
                 : "r"((a)[0]), "r"((a)[1]), "r"((a)[2]), "r"((a)[3]), \
                   "r"((b)[0]), "r"((b)[1]))

#define MMATF32(c, a0, a1, a2, a3, b0, b1) \
    asm volatile("mma.sync.aligned.m16n8k8.row.col.f32.tf32.tf32.f32 " \
                 "{%0,%1,%2,%3}, {%4,%5,%6,%7}, {%8,%9}, {%0,%1,%2,%3};" \
                 : "+f"((c)[0]), "+f"((c)[1]), "+f"((c)[2]), "+f"((c)[3]) \
                 : "r"(a0), "r"(a1), "r"(a2), "r"(a3), "r"(b0), "r"(b1))

#define LDMX4(r0, r1, r2, r3, a) \
    asm volatile("ldmatrix.sync.aligned.m8n8.x4.shared.b16 {%0,%1,%2,%3}, [%4];" \
                 : "=r"(r0), "=r"(r1), "=r"(r2), "=r"(r3) : "r"(a))
#define LDMX4T(r0, r1, r2, r3, a) \
    asm volatile("ldmatrix.sync.aligned.m8n8.x4.trans.shared.b16 {%0,%1,%2,%3}, [%4];" \
                 : "=r"(r0), "=r"(r1), "=r"(r2), "=r"(r3) : "r"(a))

__device__ __forceinline__ float gelu_tanh(float x) {
    const float c = 0.7978845608028654f;
    float x3 = x * x * x;
    return 0.5f * x * (1.0f + tanhf(c * (x + 0.044715f * x3)));
}
__device__ __forceinline__ void lse_merge(float& m, float& s, float m2, float s2) {
    float M = fmaxf(m, m2);
    if (M == -INFINITY) { m = M; s = 0.f; return; }
    float e1 = (m  == -INFINITY) ? 0.f : expf(m  - M);
    float e2 = (m2 == -INFINITY) ? 0.f : expf(m2 - M);
    s = s * e1 + s2 * e2;
    m = M;
}

// ---------------- embed ---------------------------------------------------------
__global__ void embed_kernel(const int* __restrict__ x0,
                             const float* __restrict__ wte,
                             const float* __restrict__ wpe,
                             float* __restrict__ x) {
    int i = blockIdx.x * blockDim.x + threadIdx.x;
    if (i >= NM * NE) return;
    int tok = i / NE, e = i - tok * NE;
    int t = tok % NTOK;
    int id = x0[tok];
    x[i] = wte[(size_t)id * NE + e] + wpe[(size_t)t * NE + e];
}

// ---------------- layernorm -> tf32 fp32, K-permuted output ------------------------
__global__ void __launch_bounds__(256) ln_f32(const float* __restrict__ x,
                                              const float* __restrict__ w,
                                              const float* __restrict__ b,
                                              float* __restrict__ out) {
    int warp = threadIdx.x >> 5, lane = threadIdx.x & 31;
    int tok = blockIdx.x * 8 + warp;
    const float* row = x + (size_t)tok * NE;

    float v[24];
    float s = 0.f;
#pragma unroll
    for (int j = 0; j < 6; ++j) {
        float4 f = *(const float4*)(row + j * 128 + lane * 4);
        v[4*j] = f.x; v[4*j+1] = f.y; v[4*j+2] = f.z; v[4*j+3] = f.w;
        s += (f.x + f.y) + (f.z + f.w);
    }
#pragma unroll
    for (int o = 16; o > 0; o >>= 1) s += __shfl_xor_sync(0xFFFFFFFFu, s, o);
    float mean = s * (1.0f / NE);

    float var = 0.f;
#pragma unroll
    for (int i = 0; i < 24; ++i) { float d = v[i] - mean; var += d * d; }
#pragma unroll
    for (int o = 16; o > 0; o >>= 1) var += __shfl_xor_sync(0xFFFFFFFFu, var, o);
    float rstd = rsqrtf(var * (1.0f / NE) + 1e-6f);

    // old col = j*128 + lane*4 + i -> new pos = j*128 + (lane/2)*8 + 2i + (lane&1)
    int gb = (lane >> 1) * 8 + (lane & 1);
#pragma unroll
    for (int j = 0; j < 6; ++j) {
        float4 w4 = *(const float4*)(w + j * 128 + lane * 4);
        float4 b4 = *(const float4*)(b + j * 128 + lane * 4);
        float* o = out + (size_t)tok * NE + j * 128 + gb;
        *(uint32_t*)(o + 0) = tf32r((v[4*j]   - mean) * rstd * w4.x + b4.x);
        *(uint32_t*)(o + 2) = tf32r((v[4*j+1] - mean) * rstd * w4.y + b4.y);
        *(uint32_t*)(o + 4) = tf32r((v[4*j+2] - mean) * rstd * w4.z + b4.z);
        *(uint32_t*)(o + 6) = tf32r((v[4*j+3] - mean) * rstd * w4.w + b4.w);
    }
}

// ---------------- tf32 round + K-permute (wte) -------------------------------------
__global__ void tf32round(const float* __restrict__ x, float* __restrict__ y, int n8) {
    int i = blockIdx.x * blockDim.x + threadIdx.x;
    if (i >= n8) return;
    float4 lo = ((const float4*)x)[i * 2];
    float4 hi = ((const float4*)x)[i * 2 + 1];
    uint4 w0, w1;
    w0.x = tf32r(lo.x); w0.y = tf32r(hi.x); w0.z = tf32r(lo.y); w0.w = tf32r(hi.y);
    w1.x = tf32r(lo.z); w1.y = tf32r(hi.z); w1.z = tf32r(lo.w); w1.w = tf32r(hi.w);
    ((uint4*)y)[i * 2]     = w0;
    ((uint4*)y)[i * 2 + 1] = w1;
}

// ---------------- batched transpose + tf32 + K-permute (weights, all layers) -------
// in[z][K,N] -> out[z][N,K]; blockIdx.z = layer, outStride = per-layer out offset.
__global__ void __launch_bounds__(256) ttf32b(const float* __restrict__ in,
                                              float* __restrict__ out,
                                              int K, int N, size_t outStride) {
    __shared__ float t[32][65];
    int tid = threadIdx.x;
    int kb = blockIdx.y * 32, nb = blockIdx.x * 64;
    in  += (size_t)blockIdx.z * K * N;
    out += (size_t)blockIdx.z * outStride;
#pragma unroll
    for (int i = 0; i < 2; ++i) {
        int id = tid + 256 * i;
        int r = id >> 4, c4 = (id & 15) * 4;
        float4 v = *(const float4*)(in + (size_t)(kb + r) * N + nb + c4);
        t[r][c4] = v.x; t[r][c4+1] = v.y; t[r][c4+2] = v.z; t[r][c4+3] = v.w;
    }
    __syncthreads();
#pragma unroll
    for (int i = 0; i < 8; ++i) {
        int id = tid + 256 * i;
        int n = id >> 5, kp = id & 31;
        uint32_t o = tf32r(t[kp][n]);
        int kpp = (kp & 24) | QP(kp & 7);
        *(uint32_t*)(out + (size_t)(nb + n) * K + kb + kpp) = o;
    }
}

// ---------------- TF32 GEMM (K-permuted operands, LDS.64 fragments) ----------------
// EPI: 0 = split-bf16 out; 1 = +R fp32 out; 2 = gelu tf32 K-permuted out;
//      3 = fp32 out + lse partials. BN = 128 or 64. smem pad = 40 floats.
template<int EPI, int BN>
__global__ void __launch_bounds__(256, 2) gemm_t32(
    const float* __restrict__ A, const float* __restrict__ B,
    float* __restrict__ C, bf16* __restrict__ Ch, bf16* __restrict__ Cl,
    const float* __restrict__ R,
    float* __restrict__ PM, float* __restrict__ PS,
    int M, int N, int K)
{
    constexpr int NT = BN / 32;
    extern __shared__ float smf[];
    float* As = smf;                     // [2][128][40]
    float* Bs = smf + 2 * 128 * 40;      // [2][BN][40]
    const uint32_t* Au = (const uint32_t*)As;
    const uint32_t* Bu = (const uint32_t*)Bs;

    const int tid = threadIdx.x;
    const int lane = tid & 31, wid = tid >> 5;
    const int wm = wid >> 2, wn = wid & 3;
    const int g = lane >> 2, tg = lane & 3;
    const int m0 = blockIdx.x * 128;
    const int n0 = blockIdx.y * BN;

    float acc[4][NT][4];
#pragma unroll
    for (int a = 0; a < 4; ++a)
#pragma unroll
        for (int b = 0; b < NT; ++b)
#pragma unroll
            for (int c = 0; c < 4; ++c) acc[a][b][c] = 0.f;

    auto load_stage = [&](int st, int k0) {
#pragma unroll
        for (int i = 0; i < 4; ++i) {
            int id = tid + 256 * i;
            int r = id >> 3, u = id & 7;
            cpa16(&As[(st * 128 + r) * 40 + u * 4], A + (size_t)(m0 + r) * K + k0 + u * 4);
        }
#pragma unroll
        for (int i = 0; i < BN / 32; ++i) {
            int id = tid + 256 * i;
            int r = id >> 3, u = id & 7;
            int n = n0 + r;
            int ok = n < N;
            cpa16z(&Bs[(st * BN + r) * 40 + u * 4],
                   B + (size_t)(ok ? n : 0) * K + k0 + u * 4, ok ? 16 : 0);
        }
    };

    load_stage(0, 0);
    CP_COMMIT();
    const int nk = K / 32;
    for (int it = 0; it < nk; ++it) {
        int st = it & 1;
        if (it + 1 < nk) { load_stage(st ^ 1, (it + 1) * 32); CP_COMMIT(); CP_WAIT(1); }
        else            { CP_WAIT(0); }
        __syncthreads();
#pragma unroll
        for (int k8 = 0; k8 < 32; k8 += 8) {
            uint2 bfv[NT];
#pragma unroll
            for (int nt = 0; nt < NT; ++nt) {
                int row = st * BN + wn * (BN / 4) + nt * 8 + g;
                bfv[nt] = *(const uint2*)&Bu[row * 40 + k8 + 2 * tg];
            }
#pragma unroll
            for (int mt = 0; mt < 4; ++mt) {
                int row = st * 128 + wm * 64 + mt * 16 + g;
                uint2 aA = *(const uint2*)&Au[row * 40 + k8 + 2 * tg];
                uint2 aB = *(const uint2*)&Au[(row + 8) * 40 + k8 + 2 * tg];
#pragma unroll
                for (int nt = 0; nt < NT; ++nt)
                    MMATF32(acc[mt][nt], aA.x, aB.x, aA.y, aB.y, bfv[nt].x, bfv[nt].y);
            }
        }
        __syncthreads();
    }

    if (EPI == 3) {
        int tile = blockIdx.y * 4 + wn;
#pragma unroll
        for (int mt = 0; mt < 4; ++mt) {
#pragma unroll
            for (int r = 0; r < 2; ++r) {
                int m = m0 + wm * 64 + mt * 16 + g + 8 * r;
                float vals[2 * NT];
                float rm = -INFINITY;
#pragma unroll
                for (int nt = 0; nt < NT; ++nt)
#pragma unroll
                    for (int j = 0; j < 2; ++j) {
                        int n = n0 + wn * (BN / 4) + nt * 8 + 2 * tg + j;
                        float v = acc[mt][nt][2 * r + j];
                        if (n < N) {
                            C[(size_t)m * N + n] = v;
                            rm = fmaxf(rm, v);
                            vals[nt * 2 + j] = v;
                        } else {
                            vals[nt * 2 + j] = -INFINITY;
                        }
                    }
                rm = fmaxf(rm, __shfl_xor_sync(0xFFFFFFFFu, rm, 1));
                rm = fmaxf(rm, __shfl_xor_sync(0xFFFFFFFFu, rm, 2));
                float s = 0.f;
                if (rm != -INFINITY) {
#pragma unroll
                    for (int i = 0; i < 2 * NT; ++i)
                        s += (vals[i] == -INFINITY) ? 0.f : expf(vals[i] - rm);
                }
                s += __shfl_xor_sync(0xFFFFFFFFu, s, 1);
                s += __shfl_xor_sync(0xFFFFFFFFu, s, 2);
                if (tg == 0) {
                    PM[(size_t)m * NTP + tile] = rm;
                    PS[(size_t)m * NTP + tile] = s;
                }
            }
        }
        return;
    }

#pragma unroll
    for (int mt = 0; mt < 4; ++mt) {
#pragma unroll
        for (int nt = 0; nt < NT; ++nt) {
            int nbase = n0 + wn * (BN / 4) + nt * 8 + 2 * tg;
#pragma unroll
            for (int r = 0; r < 2; ++r) {
                int m = m0 + wm * 64 + mt * 16 + g + 8 * r;
                float v0 = acc[mt][nt][2 * r + 0];
                float v1 = acc[mt][nt][2 * r + 1];
                if (EPI == 0) {
                    bf16 h0 = __float2bfloat16(v0);
                    bf16 h1 = __float2bfloat16(v1);
                    __nv_bfloat162 hp; hp.x = h0; hp.y = h1;
                    *(uint32_t*)(Ch + (size_t)m * N + nbase) = *(uint32_t*)&hp;
                    *(uint32_t*)(Cl + (size_t)m * N + nbase) =
                        packbf(v0 - __bfloat162float(h0), v1 - __bfloat162float(h1));
                } else if (EPI == 1) {
                    v0 += R[(size_t)m * N + nbase];
                    v1 += R[(size_t)m * N + nbase + 1];
                    C[(size_t)m * N + nbase]     = v0;
                    C[(size_t)m * N + nbase + 1] = v1;
                } else {  // EPI == 2: gelu, K-permuted store (feeds Proj's K)
                    int nb8 = n0 + wn * (BN / 4) + nt * 8;
                    *(uint32_t*)(C + (size_t)m * N + nb8 + QP(2 * tg))     =
                        tf32r(gelu_tanh(v0));
                    *(uint32_t*)(C + (size_t)m * N + nb8 + QP(2 * tg + 1)) =
                        tf32r(gelu_tanh(v1));
                }
            }
        }
    }
}

// ---------------- flash attention with split-KV load balancing ---------------------
#define FP2 72
#define FTILE (64*FP2)
#define FSTG (4*FTILE)
#define FSMEM (2*FSTG*2)

__global__ void __launch_bounds__(128) flash2(
    const bf16* __restrict__ qh, const bf16* __restrict__ ql,
    float* __restrict__ yf, float* __restrict__ po,
    float* __restrict__ pmx, float* __restrict__ pll)
{
    extern __shared__ bf16 fsm[];
    const int u = blockIdx.x;
    const int bh = blockIdx.y, b = bh / NH, h = bh % NH;
    int qt, sb0, sb1, mode;
    if (u < 8)       { mode = 1; qt = 8 + u;        sb0 = 0; sb1 = 7;  }
    else if (u < 16) { mode = 2; qt = 15 - (u - 8); sb0 = 8; sb1 = qt; }
    else             { mode = 0; qt = 23 - u;       sb0 = 0; sb1 = qt; }
    const int t0 = qt * 64;
    const int tid = threadIdx.x, lane = tid & 31, w = tid >> 5;
    const int g = lane >> 2, tg = lane & 3;
    const uint32_t smb = smem_u32(fsm);

    uint32_t qfh[4][4], qfl[4][4];
    {
        const size_t base = (size_t)(b * NTOK + t0 + w * 16) * N3 + h * DH;
#pragma unroll
        for (int kf = 0; kf < 4; ++kf) {
            int c0 = kf * 16 + 2 * tg;
            qfh[kf][0] = *(const uint32_t*)(qh + base + (size_t)g * N3 + c0);
            qfh[kf][1] = *(const uint32_t*)(qh + base + (size_t)(g + 8) * N3 + c0);
            qfh[kf][2] = *(const uint32_t*)(qh + base + (size_t)g * N3 + c0 + 8);
            qfh[kf][3] = *(const uint32_t*)(qh + base + (size_t)(g + 8) * N3 + c0 + 8);
            qfl[kf][0] = *(const uint32_t*)(ql + base + (size_t)g * N3 + c0);
            qfl[kf][1] = *(const uint32_t*)(ql + base + (size_t)(g + 8) * N3 + c0);
            qfl[kf][2] = *(const uint32_t*)(ql + base + (size_t)g * N3 + c0 + 8);
            qfl[kf][3] = *(const uint32_t*)(ql + base + (size_t)(g + 8) * N3 + c0 + 8);
        }
    }

    auto loadKV = [&](int st, int sb) {
        int s0 = sb * 64;
#pragma unroll
        for (int i = 0; i < 16; ++i) {
            int id = tid + 128 * i;
            int tile = id >> 9;
            int rem = id & 511;
            int r = rem >> 3, c8 = (rem & 7) * 8;
            uint32_t dst = smb + (uint32_t)(st * FSTG + tile * FTILE + r * FP2 + c8) * 2;
            size_t rowoff = (size_t)(b * NTOK + s0 + r) * N3 + h * DH + c8;
            const bf16* src =
                (tile == 0) ? qh + rowoff + NE :
                (tile == 1) ? ql + rowoff + NE :
                (tile == 2) ? qh + rowoff + 2 * NE :
                              ql + rowoff + 2 * NE;
            cpa16u(dst, src);
        }
    };

    float mr[2] = {-1e30f, -1e30f};
    float lr[2] = {0.f, 0.f};
    float acco[8][4];
#pragma unroll
    for (int i = 0; i < 8; ++i)
#pragma unroll
        for (int j = 0; j < 4; ++j) acco[i][j] = 0.f;

    loadKV(0, sb0);
    CP_COMMIT();

    const int krow = ((lane >> 4) << 3) + (lane & 7);
    const int kcol = ((lane >> 3) & 1) * 8;
    const int vrow = lane & 15;
    const int vcol = (lane >> 4) * 8;

    for (int sb = sb0; sb <= sb1; ++sb) {
        int st = (sb - sb0) & 1;
        if (sb + 1 <= sb1) { loadKV(st ^ 1, sb + 1); CP_COMMIT(); CP_WAIT(1); }
        else               { CP_WAIT(0); }
        __syncthreads();

        const uint32_t kb  = smb + (uint32_t)(st * FSTG) * 2;
        const uint32_t kbl = kb + FTILE * 2;
        const uint32_t vb  = kb + 2 * FTILE * 2;
        const uint32_t vbl = kb + 3 * FTILE * 2;

        float accs[8][4];
#pragma unroll
        for (int i = 0; i < 8; ++i)
#pragma unroll
            for (int j = 0; j < 4; ++j) accs[i][j] = 0.f;
#pragma unroll
        for (int ntp = 0; ntp < 4; ++ntp) {
#pragma unroll
            for (int kf = 0; kf < 4; ++kf) {
                uint32_t off = (uint32_t)((ntp * 16 + krow) * FP2 + kf * 16 + kcol) * 2;
                uint32_t h0, h1, h2, h3, l0, l1, l2, l3;
                LDMX4(h0, h1, h2, h3, kb + off);
                LDMX4(l0, l1, l2, l3, kbl + off);
                uint32_t bh0[2] = {h0, h1}, bh1[2] = {h2, h3};
                uint32_t bl0[2] = {l0, l1}, bl1[2] = {l2, l3};
                MMA16816(accs[2*ntp],     qfh[kf], bh0);
                MMA16816(accs[2*ntp + 1], qfh[kf], bh1);
                MMA16816(accs[2*ntp],     qfh[kf], bl0);
                MMA16816(accs[2*ntp + 1], qfh[kf], bl1);
                MMA16816(accs[2*ntp],     qfl[kf], bh0);
                MMA16816(accs[2*ntp + 1], qfl[kf], bh1);
            }
        }

        int s0 = sb * 64;
#pragma unroll
        for (int r = 0; r < 2; ++r) {
            int row = t0 + w * 16 + g + 8 * r;
            float rm = -1e30f;
#pragma unroll
            for (int nt = 0; nt < 8; ++nt) {
#pragma unroll
                for (int j = 0; j < 2; ++j) {
                    int col = s0 + nt * 8 + 2 * tg + j;
                    float v = accs[nt][2 * r + j] * 0.125f;
                    if (col > row) v = -1e30f;
                    accs[nt][2 * r + j] = v;
                    rm = fmaxf(rm, v);
                }
            }
            rm = fmaxf(rm, __shfl_xor_sync(0xFFFFFFFFu, rm, 1));
            rm = fmaxf(rm, __shfl_xor_sync(0xFFFFFFFFu, rm, 2));
            float nm = fmaxf(mr[r], rm);
            float fac = __expf(mr[r] - nm);
            mr[r] = nm;
            float rs = 0.f;
#pragma unroll
            for (int nt = 0; nt < 8; ++nt) {
#pragma unroll
                for (int j = 0; j < 2; ++j) {
                    float p = __expf(accs[nt][2 * r + j] - nm);
                    accs[nt][2 * r + j] = p;
                    rs += p;
                }
            }
            rs += __shfl_xor_sync(0xFFFFFFFFu, rs, 1);
            rs += __shfl_xor_sync(0xFFFFFFFFu, rs, 2);
            lr[r] = lr[r] * fac + rs;
#pragma unroll
            for (int nt = 0; nt < 8; ++nt) {
                acco[nt][2 * r + 0] *= fac;
                acco[nt][2 * r + 1] *= fac;
            }
        }

#pragma unroll
        for (int kf2 = 0; kf2 < 4; ++kf2) {
            uint32_t pah[4], pal[4];
            float p00 = accs[2 * kf2][0],     p01 = accs[2 * kf2][1];
            float p10 = accs[2 * kf2][2],     p11 = accs[2 * kf2][3];
            float p20 = accs[2 * kf2 + 1][0], p21 = accs[2 * kf2 + 1][1];
            float p30 = accs[2 * kf2 + 1][2], p31 = accs[2 * kf2 + 1][3];
            pah[0] = packbf(p00, p01); pah[1] = packbf(p10, p11);
            pah[2] = packbf(p20, p21); pah[3] = packbf(p30, p31);
            __nv_bfloat162* hp;
            hp = (__nv_bfloat162*)&pah[0];
            pal[0] = packbf(p00 - __bfloat162float(hp->x), p01 - __bfloat162float(hp->y));
            hp = (__nv_bfloat162*)&pah[1];
            pal[1] = packbf(p10 - __bfloat162float(hp->x), p11 - __bfloat162float(hp->y));
            hp = (__nv_bfloat162*)&pah[2];
            pal[2] = packbf(p20 - __bfloat162float(hp->x), p21 - __bfloat162float(hp->y));
            hp = (__nv_bfloat162*)&pah[3];
            pal[3] = packbf(p30 - __bfloat162float(hp->x), p31 - __bfloat162float(hp->y));
#pragma unroll
            for (int ntp2 = 0; ntp2 < 4; ++ntp2) {
                uint32_t off = (uint32_t)((kf2 * 16 + vrow) * FP2 + ntp2 * 16 + vcol) * 2;
                uint32_t h0, h1, h2, h3, l0, l1, l2, l3;
                LDMX4T(h0, h1, h2, h3, vb + off);
                LDMX4T(l0, l1, l2, l3, vbl + off);
                uint32_t vh0[2] = {h0, h1}, vh1[2] = {h2, h3};
                uint32_t vl0[2] = {l0, l1}, vl1[2] = {l2, l3};
                MMA16816(acco[2*ntp2],     pah, vh0);
                MMA16816(acco[2*ntp2 + 1], pah, vh1);
                MMA16816(acco[2*ntp2],     pah, vl0);
                MMA16816(acco[2*ntp2 + 1], pah, vl1);
                MMA16816(acco[2*ntp2],     pal, vh0);
                MMA16816(acco[2*ntp2 + 1], pal, vh1);
            }
        }
        __syncthreads();
    }

    if (mode == 0) {
        // y written K-permuted (feeds Wo GEMM A)
#pragma unroll
        for (int r = 0; r < 2; ++r) {
            float inv = 1.0f / lr[r];
            int row = t0 + w * 16 + g + 8 * r;
            float* dst = yf + (size_t)(b * NTOK + row) * NE + h * DH;
#pragma unroll
            for (int nt2 = 0; nt2 < 8; ++nt2) {
                int d8 = nt2 * 8;
                *(uint32_t*)(dst + d8 + QP(2 * tg))     = tf32r(acco[nt2][2 * r + 0] * inv);
                *(uint32_t*)(dst + d8 + QP(2 * tg + 1)) = tf32r(acco[nt2][2 * r + 1] * inv);
            }
        }
    } else {
        int part = mode - 1;
        size_t unit = ((size_t)part * NBH + bh) * 8 + (qt - 8);
#pragma unroll
        for (int r = 0; r < 2; ++r) {
            int lrow = w * 16 + g + 8 * r;
#pragma unroll
            for (int nt2 = 0; nt2 < 8; ++nt2) {
                float2 o;
                o.x = acco[nt2][2 * r + 0];
                o.y = acco[nt2][2 * r + 1];
                *(float2*)(po + unit * 4096 + lrow * 64 + nt2 * 8 + 2 * tg) = o;
            }
            if (tg == 0) {
                pmx[unit * 64 + lrow] = mr[r];
                pll[unit * 64 + lrow] = lr[r];
            }
        }
    }
}

// merge partials (exact lse combine), write K-permuted tf32 y
__global__ void __launch_bounds__(256) flash_merge(
    const float* __restrict__ po, const float* __restrict__ pmx,
    const float* __restrict__ pll, float* __restrict__ yf)
{
    int qi = blockIdx.x;
    int bh = blockIdx.y, b = bh / NH, h = bh % NH;
    int row = threadIdx.x >> 2;
    int c0 = (threadIdx.x & 3) * 16;

    size_t ua = (size_t)bh * 8 + qi;
    size_t ub = ((size_t)NBH + bh) * 8 + qi;
    float ma = pmx[ua * 64 + row], la = pll[ua * 64 + row];
    float mb = pmx[ub * 64 + row], lb = pll[ub * 64 + row];
    float M = fmaxf(ma, mb);
    float wa = __expf(ma - M), wb = __expf(mb - M);
    float inv = 1.0f / (wa * la + wb * lb);
    wa *= inv; wb *= inv;

    const float* Oa = po + ua * 4096 + row * 64 + c0;
    const float* Ob = po + ub * 4096 + row * 64 + c0;
    float* dst = yf + (size_t)(b * NTOK + (8 + qi) * 64 + row) * NE + h * DH;
#pragma unroll
    for (int i = 0; i < 16; ++i) {
        float v = wa * Oa[i] + wb * Ob[i];
        int c = c0 + i;
        *(uint32_t*)(dst + (c & 56) + QP(c & 7)) = tf32r(v);
    }
}

// ---------------- loss: merge logsumexp partials ----------------------------------
__global__ void __launch_bounds__(256) loss_rows2(const float* __restrict__ pm,
                                                  const float* __restrict__ ps,
                                                  const float* __restrict__ logits,
                                                  const int* __restrict__ tgt,
                                                  float* __restrict__ rl) {
    int row = blockIdx.x;
    int tid = threadIdx.x;
    __shared__ float sm[256], ss[256];

    float m = -INFINITY, s = 0.f;
    for (int i = tid; i < NTP; i += 256)
        lse_merge(m, s, pm[(size_t)row * NTP + i], ps[(size_t)row * NTP + i]);
    sm[tid] = m; ss[tid] = s; __syncthreads();
    for (int o = 128; o > 0; o >>= 1) {
        if (tid < o) {
            float mm = sm[tid], sv = ss[tid];
            lse_merge(mm, sv, sm[tid + o], ss[tid + o]);
            sm[tid] = mm; ss[tid] = sv;
        }
        __syncthreads();
    }
    if (tid == 0) {
        float lt = logits[(size_t)row * NV + tgt[row]];
        rl[row] = -(lt - sm[0] - logf(ss[0]));
    }
}

__global__ void __launch_bounds__(256) loss_final(const float* __restrict__ rl,
                                                  float* __restrict__ out) {
    __shared__ float red[256];
    int tid = threadIdx.x;
    float s = 0.f;
    for (int i = tid; i < NM; i += 256) s += rl[i];
    red[tid] = s; __syncthreads();
    for (int o = 128; o > 0; o >>= 1) { if (tid < o) red[tid] += red[tid + o]; __syncthreads(); }
    if (tid == 0) out[0] = red[0] * (1.0f / NM);
}

// ---------------- host orchestration ------------------------------------------------
extern "C" void kernel_launch(void* const* d_in, const int* in_sizes, int n_in,
                              void* d_out, int out_size) {
    const int*   x0    = (const int*)  d_in[0];
    const int*   tgt   = (const int*)  d_in[1];
    const float* wte   = (const float*)d_in[2];
    const float* wpe   = (const float*)d_in[3];
    const float* ln1w  = (const float*)d_in[4];
    const float* ln1b  = (const float*)d_in[5];
    const float* Wqkv  = (const float*)d_in[6];
    const float* Wo    = (const float*)d_in[7];
    const float* ln2w  = (const float*)d_in[8];
    const float* ln2b  = (const float*)d_in[9];
    const float* Wfc   = (const float*)d_in[10];
    const float* Wproj = (const float*)d_in[11];
    const float* lnfw  = (const float*)d_in[12];
    const float* lnfb  = (const float*)d_in[13];

    float *px, *pl, *prl, *ppm, *pps, *pwtef, *plnf, *pwtf, *pwtfq, *pyf, *pfcf;
    float *ppo, *ppmx, *ppll;
    bf16 *pqh, *pql;
    cudaGetSymbolAddress((void**)&px,  g_x);
    cudaGetSymbolAddress((void**)&pl,  g_logits);
    cudaGetSymbolAddress((void**)&prl, g_rl);
    cudaGetSymbolAddress((void**)&ppm, g_pm);
    cudaGetSymbolAddress((void**)&pps, g_ps);
    cudaGetSymbolAddress((void**)&pwtef, g_wtef);
    cudaGetSymbolAddress((void**)&plnf, g_lnf);
    cudaGetSymbolAddress((void**)&pwtf, g_wtf);
    cudaGetSymbolAddress((void**)&pwtfq, g_wtfq);
    cudaGetSymbolAddress((void**)&pyf,  g_yf);
    cudaGetSymbolAddress((void**)&pfcf, g_fcf);
    cudaGetSymbolAddress((void**)&ppo,  g_po);
    cudaGetSymbolAddress((void**)&ppmx, g_pmx);
    cudaGetSymbolAddress((void**)&ppll, g_pll);
    cudaGetSymbolAddress((void**)&pqh, g_qkvh);
    cudaGetSymbolAddress((void**)&pql, g_qkvl);

    const int SM_T128 = (2 * 128 * 40 + 2 * 128 * 40) * 4;   // 81920 B
    const int SM_T64  = (2 * 128 * 40 + 2 * 64  * 40) * 4;   // 61440 B
    cudaFuncSetAttribute(gemm_t32<0,128>, cudaFuncAttributeMaxDynamicSharedMemorySize, SM_T128);
    cudaFuncSetAttribute(gemm_t32<1,64>,  cudaFuncAttributeMaxDynamicSharedMemorySize, SM_T64);
    cudaFuncSetAttribute(gemm_t32<2,128>, cudaFuncAttributeMaxDynamicSharedMemorySize, SM_T128);
    cudaFuncSetAttribute(gemm_t32<3,128>, cudaFuncAttributeMaxDynamicSharedMemorySize, SM_T128);
    cudaFuncSetAttribute(flash2, cudaFuncAttributeMaxDynamicSharedMemorySize, FSMEM);

    // ---- weight prep: 4 batched launches (all layers each) + wte round -----------
    embed_kernel<<<(NM * NE + 255) / 256, 256>>>(x0, wte, wpe, px);                 // 1
    ttf32b<<<dim3(N3 / 64, NE / 32, NL), 256>>>(Wqkv, pwtfq, NE, N3, LQKV);         // 2
    ln_f32<<<NM / 8, 256>>>(px, ln1w, ln1b, plnf);                                  // 3
    gemm_t32<0,128><<<dim3(NM / 128, N3 / 128), 256, SM_T128>>>(                    // 4 (profiled)
        plnf, pwtfq, nullptr, pqh, pql, nullptr, nullptr, nullptr, NM, N3, NE);
    {
        int n8 = (NV * NE) / 8;
        tf32round<<<(n8 + 255) / 256, 256>>>(wte, pwtef, n8);
    }
    ttf32b<<<dim3(NE / 64, NE / 32, NL), 256>>>(Wo, pwtf, NE, NE, LTF);
    ttf32b<<<dim3(N4 / 64, NE / 32, NL), 256>>>(Wfc, pwtf + LWO, NE, N4, LTF);
    ttf32b<<<dim3(NE / 64, N4 / 32, NL), 256>>>(Wproj, pwtf + LWO + LWFC, N4, NE, LTF);

    // ---- layer 0 rest ----
    flash2<<<dim3(24, NBH), 128, FSMEM>>>(pqh, pql, pyf, ppo, ppmx, ppll);
    flash_merge<<<dim3(8, NBH), 256>>>(ppo, ppmx, ppll, pyf);
    gemm_t32<1,64><<<dim3(NM / 128, NE / 64), 256, SM_T64>>>(
        pyf, pwtf, px, nullptr, nullptr, px, nullptr, nullptr, NM, NE, NE);
    ln_f32<<<NM / 8, 256>>>(px, ln2w, ln2b, plnf);
    gemm_t32<2,128><<<dim3(NM / 128, N4 / 128), 256, SM_T128>>>(
        plnf, pwtf + LWO, pfcf, nullptr, nullptr, nullptr, nullptr, nullptr, NM, N4, NE);
    gemm_t32<1,64><<<dim3(NM / 128, NE / 64), 256, SM_T64>>>(
        pfcf, pwtf + LWO + LWFC, px, nullptr, nullptr, px, nullptr, nullptr, NM, NE, N4);

    // ---- layers 1..5 ----
    for (int l = 1; l < NL; ++l) {
        size_t qoff = (size_t)l * LQKV;
        size_t toff = (size_t)l * LTF;
        ln_f32<<<NM / 8, 256>>>(px, ln1w + (size_t)l * NE, ln1b + (size_t)l * NE, plnf);
        gemm_t32<0,128><<<dim3(NM / 128, N3 / 128), 256, SM_T128>>>(
            plnf, pwtfq + qoff, nullptr, pqh, pql, nullptr, nullptr, nullptr, NM, N3, NE);
        flash2<<<dim3(24, NBH), 128, FSMEM>>>(pqh, pql, pyf, ppo, ppmx, ppll);
        flash_merge<<<dim3(8, NBH), 256>>>(ppo, ppmx, ppll, pyf);
        gemm_t32<1,64><<<dim3(NM / 128, NE / 64), 256, SM_T64>>>(
            pyf, pwtf + toff, px, nullptr, nullptr, px, nullptr, nullptr, NM, NE, NE);
        ln_f32<<<NM / 8, 256>>>(px, ln2w + (size_t)l * NE, ln2b + (size_t)l * NE, plnf);
        gemm_t32<2,128><<<dim3(NM / 128, N4 / 128), 256, SM_T128>>>(
            plnf, pwtf + toff + LWO, pfcf, nullptr, nullptr, nullptr, nullptr, nullptr,
            NM, N4, NE);
        gemm_t32<1,64><<<dim3(NM / 128, NE / 64), 256, SM_T64>>>(
            pfcf, pwtf + toff + LWO + LWFC, px, nullptr, nullptr, px, nullptr, nullptr,
            NM, NE, N4);
    }

    ln_f32<<<NM / 8, 256>>>(px, lnfw, lnfb, plnf);

    const size_t logits_elems = (size_t)NM * NV;
    float* logits = ((size_t)out_size >= logits_elems) ? (float*)d_out : pl;
    gemm_t32<3,128><<<dim3(NM / 128, NTN), 256, SM_T128>>>(
        plnf, pwtef, logits, nullptr, nullptr, nullptr, ppm, pps, NM, NV, NE);

    loss_rows2<<<NM, 256>>>(ppm, pps, logits, tgt, prl);
    if ((size_t)out_size > logits_elems) {
        loss_final<<<1, 256>>>(prl, (float*)d_out + logits_elems);
    } else if (logits != (float*)d_out) {
        loss_final<<<1, 256>>>(prl, (float*)d_out);
    }
}